// round 4
// baseline (speedup 1.0000x reference)
#include <cuda_runtime.h>
#include <cstdint>

// ---------------------------------------------------------------------------
// SpatioTemporalAttention on GB300 — Round 2 baseline
//
// Pipeline (all fp32):
//   1. Q = x_q  @ Wq + bq                     (GEMM 32768x1024x1024)
//   2. K = x_kv @ Wk + bk                     (GEMM)
//   3. V = x_kv @ Wv + bv                     (GEMM)
//   4. S = (Q @ Wqa + bqa)*scale              (logits, [32768,16])
//   5. pooled_q[n,c] = softmax_L(S) . Q       (softpool)
//   6. S = ((K*pooled_q) @ Wka + bka)*scale   (gated logits)
//   7. pooled_k[n,c] = softmax_L(S) . K       (softpool)
//   8. T = (V*pooled_k) @ Wt + bt             (GEMM, gate folded into A load,
//                                              written into K's buffer)
//   9. out = (T + Q) @ Wp + bp                (GEMM, residual folded into A load)
// ---------------------------------------------------------------------------

#define C_DIM 1024
#define H_DIM 16
#define DH_DIM 64
#define NB 8
#define LSEQ 4096
#define MTOT (NB * LSEQ)   // 32768

// Scratch (device globals — no allocations allowed)
__device__ float g_Q[(size_t)MTOT * C_DIM];   // queries (needed until step 9)
__device__ float g_K[(size_t)MTOT * C_DIM];   // keys, reused as T after step 7
__device__ float g_V[(size_t)MTOT * C_DIM];   // values
__device__ float g_S[(size_t)MTOT * H_DIM];   // attention logits
__device__ float g_pq[NB * C_DIM];            // pooled_q (grouped [N,C])
__device__ float g_pk[NB * C_DIM];            // pooled_k (grouped [N,C])

union F2U { unsigned long long u; float2 f; };

// ---------------------------------------------------------------------------
// SGEMM: C[M,N] = op(A)[M,K] @ B[K,N] + bias[N]
//   GATE: A element (row,k) multiplied by gate[(row/LSEQ)*C_DIM + k]
//   ADD : A element (row,k) gets addend[row*K + k] added
// BM=BN=128, BK=8, 256 threads, 8x8 per-thread microtile, f32x2 packed FMA.
// Requires M%128==0, N%128==0, K%8==0, LSEQ%128==0.
// ---------------------------------------------------------------------------
template <bool GATE, bool ADD>
__global__ __launch_bounds__(256, 2)
void sgemm_kernel(const float* __restrict__ A, const float* __restrict__ B,
                  const float* __restrict__ bias, float* __restrict__ Cc,
                  const float* __restrict__ gate, const float* __restrict__ addend,
                  int M, int N, int K)
{
    __shared__ float As[8][128];   // [k][m] (transposed)
    __shared__ float Bs[8][128];   // [k][n]

    const int tid  = threadIdx.x;
    const int m0   = blockIdx.y * 128;
    const int n0   = blockIdx.x * 128;
    const int trow = tid >> 4;           // 0..15
    const int tcol = tid & 15;           // 0..15
    const int arow = tid >> 1;           // 0..127
    const int acol = (tid & 1) * 4;      // 0 or 4
    const int brow = tid >> 5;           // 0..7
    const int bcol = (tid & 31) * 4;     // 0..124

    const float* gptr = nullptr;
    if (GATE) gptr = gate + (size_t)(m0 / LSEQ) * C_DIM;

    const float* Ag = A + (size_t)(m0 + arow) * K + acol;
    const float* Ad = nullptr;
    if (ADD) Ad = addend + (size_t)(m0 + arow) * K + acol;
    const float* Bg = B + (size_t)brow * N + n0 + bcol;

    unsigned long long acc[8][4];
    #pragma unroll
    for (int i = 0; i < 8; i++)
        #pragma unroll
        for (int j = 0; j < 4; j++) acc[i][j] = 0ull;

    for (int k0 = 0; k0 < K; k0 += 8) {
        float4 a4 = *(const float4*)(Ag + k0);
        if (ADD) {
            float4 d4 = *(const float4*)(Ad + k0);
            a4.x += d4.x; a4.y += d4.y; a4.z += d4.z; a4.w += d4.w;
        }
        if (GATE) {
            float4 g4 = *(const float4*)(gptr + k0 + acol);
            a4.x *= g4.x; a4.y *= g4.y; a4.z *= g4.z; a4.w *= g4.w;
        }
        As[acol + 0][arow] = a4.x;
        As[acol + 1][arow] = a4.y;
        As[acol + 2][arow] = a4.z;
        As[acol + 3][arow] = a4.w;

        *(float4*)&Bs[brow][bcol] = *(const float4*)(Bg + (size_t)k0 * N);
        __syncthreads();

        #pragma unroll
        for (int kk = 0; kk < 8; kk++) {
            float a_s[8];
            #pragma unroll
            for (int i = 0; i < 8; i++) a_s[i] = As[kk][trow * 8 + i];

            F2U bfr[4];
            const float2* bp2 = (const float2*)&Bs[kk][tcol * 8];
            #pragma unroll
            for (int j = 0; j < 4; j++) bfr[j].f = bp2[j];

            #pragma unroll
            for (int i = 0; i < 8; i++) {
                F2U ap; ap.f = make_float2(a_s[i], a_s[i]);
                #pragma unroll
                for (int j = 0; j < 4; j++) {
                    asm("fma.rn.f32x2 %0, %1, %2, %0;"
                        : "+l"(acc[i][j]) : "l"(ap.u), "l"(bfr[j].u));
                }
            }
        }
        __syncthreads();
    }

    float bias_r[8];
    #pragma unroll
    for (int j = 0; j < 8; j++) bias_r[j] = bias[n0 + tcol * 8 + j];

    #pragma unroll
    for (int i = 0; i < 8; i++) {
        float vals[8];
        #pragma unroll
        for (int j = 0; j < 4; j++) {
            F2U r; r.u = acc[i][j];
            vals[2 * j]     = r.f.x + bias_r[2 * j];
            vals[2 * j + 1] = r.f.y + bias_r[2 * j + 1];
        }
        float4* cp = (float4*)(Cc + (size_t)(m0 + trow * 8 + i) * N + n0 + tcol * 8);
        cp[0] = make_float4(vals[0], vals[1], vals[2], vals[3]);
        cp[1] = make_float4(vals[4], vals[5], vals[6], vals[7]);
    }
}

// ---------------------------------------------------------------------------
// Logits: S[row,h] = ((X[row,:] (* gate[batch,:])) @ W[:,16] + b[h]) * scale
// One warp per row; 8 warps/block; grid = MTOT/8 = 4096.
// ---------------------------------------------------------------------------
template <bool GATE>
__global__ __launch_bounds__(256)
void logits_kernel(const float* __restrict__ X, const float* __restrict__ W,
                   const float* __restrict__ b, const float* __restrict__ gate,
                   float* __restrict__ S)
{
    const int warp = threadIdx.x >> 5, lane = threadIdx.x & 31;
    const int row  = blockIdx.x * 8 + warp;
    const int bat  = row >> 12;   // row / 4096
    const float* xp = X + (size_t)row * C_DIM;
    const float* gp = GATE ? (gate + (size_t)bat * C_DIM) : nullptr;

    float acc[16];
    #pragma unroll
    for (int h = 0; h < 16; h++) acc[h] = 0.f;

    for (int c = lane; c < C_DIM; c += 32) {
        float a = xp[c];
        if (GATE) a *= gp[c];
        const float4* wp = (const float4*)(W + (size_t)c * 16);
        float4 w0 = wp[0], w1 = wp[1], w2 = wp[2], w3 = wp[3];
        acc[0]  += a * w0.x; acc[1]  += a * w0.y; acc[2]  += a * w0.z; acc[3]  += a * w0.w;
        acc[4]  += a * w1.x; acc[5]  += a * w1.y; acc[6]  += a * w1.z; acc[7]  += a * w1.w;
        acc[8]  += a * w2.x; acc[9]  += a * w2.y; acc[10] += a * w2.z; acc[11] += a * w2.w;
        acc[12] += a * w3.x; acc[13] += a * w3.y; acc[14] += a * w3.z; acc[15] += a * w3.w;
    }
    #pragma unroll
    for (int h = 0; h < 16; h++)
        #pragma unroll
        for (int off = 16; off; off >>= 1)
            acc[h] += __shfl_xor_sync(0xffffffffu, acc[h], off);

    if (lane == 0) {
        const float scale = 0.125f;   // 1/sqrt(DH)
        #pragma unroll
        for (int h = 0; h < 16; h++)
            S[(size_t)row * 16 + h] = (acc[h] + b[h]) * scale;
    }
}

// ---------------------------------------------------------------------------
// Softmax over L + weighted pooling.
// pooled[n, h*64+d] = sum_l softmax_l(S[n,l,h]) * X[n,l, h*64+d]
// grid = NB*H = 128, block = 256 (4 l-groups x 64 d-threads).
// ---------------------------------------------------------------------------
__global__ __launch_bounds__(256)
void softpool_kernel(const float* __restrict__ S, const float* __restrict__ X,
                     float* __restrict__ pooled)
{
    __shared__ float red[256];
    const int nh = blockIdx.x, n = nh >> 4, h = nh & 15;
    const int tid = threadIdx.x;
    const float* sp = S + (size_t)n * LSEQ * 16 + h;

    // pass 1: max over L
    float m = -1e30f;
    for (int l = tid; l < LSEQ; l += 256) m = fmaxf(m, sp[(size_t)l * 16]);
    red[tid] = m; __syncthreads();
    for (int s = 128; s; s >>= 1) { if (tid < s) red[tid] = fmaxf(red[tid], red[tid + s]); __syncthreads(); }
    m = red[0]; __syncthreads();

    // pass 2: sum of exp
    float sum = 0.f;
    for (int l = tid; l < LSEQ; l += 256) sum += __expf(sp[(size_t)l * 16] - m);
    red[tid] = sum; __syncthreads();
    for (int s = 128; s; s >>= 1) { if (tid < s) red[tid] += red[tid + s]; __syncthreads(); }
    const float invZ = 1.f / red[0]; __syncthreads();

    // pass 3: weighted pooling
    const int d = tid & 63, lg = tid >> 6;
    const float* xp = X + (size_t)n * LSEQ * C_DIM + h * 64 + d;
    float acc = 0.f;
    for (int l = lg; l < LSEQ; l += 4) {
        float w = __expf(sp[(size_t)l * 16] - m) * invZ;
        acc += w * xp[(size_t)l * C_DIM];
    }
    red[tid] = acc; __syncthreads();
    if (tid < 64)
        pooled[(size_t)n * C_DIM + h * 64 + d] =
            red[d] + red[64 + d] + red[128 + d] + red[192 + d];
}

// ---------------------------------------------------------------------------
extern "C" void kernel_launch(void* const* d_in, const int* in_sizes, int n_in,
                              void* d_out, int out_size)
{
    const float* x_q  = (const float*)d_in[0];
    const float* x_kv = (const float*)d_in[1];
    const float* Wq   = (const float*)d_in[2];
    const float* bq   = (const float*)d_in[3];
    const float* Wqa  = (const float*)d_in[4];
    const float* bqa  = (const float*)d_in[5];
    const float* Wk   = (const float*)d_in[6];
    const float* bk   = (const float*)d_in[7];
    const float* Wka  = (const float*)d_in[8];
    const float* bka  = (const float*)d_in[9];
    const float* Wv   = (const float*)d_in[10];
    const float* bv   = (const float*)d_in[11];
    const float* Wt   = (const float*)d_in[12];
    const float* bt   = (const float*)d_in[13];
    const float* Wp   = (const float*)d_in[14];
    const float* bp   = (const float*)d_in[15];
    float* out = (float*)d_out;

    float *Q, *K, *V, *S, *pq, *pk;
    cudaGetSymbolAddress((void**)&Q,  g_Q);
    cudaGetSymbolAddress((void**)&K,  g_K);
    cudaGetSymbolAddress((void**)&V,  g_V);
    cudaGetSymbolAddress((void**)&S,  g_S);
    cudaGetSymbolAddress((void**)&pq, g_pq);
    cudaGetSymbolAddress((void**)&pk, g_pk);

    dim3 gg(C_DIM / 128, MTOT / 128);   // (8, 256)

    // 1-3: projection GEMMs
    sgemm_kernel<false, false><<<gg, 256>>>(x_q,  Wq, bq, Q, nullptr, nullptr, MTOT, C_DIM, C_DIM);
    sgemm_kernel<false, false><<<gg, 256>>>(x_kv, Wk, bk, K, nullptr, nullptr, MTOT, C_DIM, C_DIM);
    sgemm_kernel<false, false><<<gg, 256>>>(x_kv, Wv, bv, V, nullptr, nullptr, MTOT, C_DIM, C_DIM);

    // 4-5: query softmax pooling
    logits_kernel<false><<<MTOT / 8, 256>>>(Q, Wqa, bqa, nullptr, S);
    softpool_kernel<<<NB * H_DIM, 256>>>(S, Q, pq);

    // 6-7: gated key softmax pooling
    logits_kernel<true><<<MTOT / 8, 256>>>(K, Wka, bka, pq, S);
    softpool_kernel<<<NB * H_DIM, 256>>>(S, K, pk);

    // 8: T = (V * pooled_k) @ Wt + bt   (into K's buffer)
    sgemm_kernel<true, false><<<gg, 256>>>(V, Wt, bt, K, pk, nullptr, MTOT, C_DIM, C_DIM);

    // 9: out = (T + Q) @ Wp + bp
    sgemm_kernel<false, true><<<gg, 256>>>(K, Wp, bp, out, nullptr, Q, MTOT, C_DIM, C_DIM);
}

// round 10
// speedup vs baseline: 2.5219x; 2.5219x over previous
#include <cuda_runtime.h>
#include <cuda_bf16.h>
#include <cstdint>

#define C_DIM 1024
#define NB 8
#define LSEQ 4096
#define MTOT (NB * LSEQ)   // 32768
#define BM 128
#define BN 128
#define KC 64
#define NCHUNK (C_DIM / KC)          // 16
#define STAGE_BYTES (64 * 1024)      // Ah 16K | Al 16K | Bh 16K | Bl 16K
#define DSMEM (1024 + 2 * STAGE_BYTES)

// ---------------- scratch --------------------------------------------------
__device__ float4 g_Q4 [(size_t)MTOT * C_DIM / 4];
__device__ float4 g_K4 [(size_t)MTOT * C_DIM / 4];
__device__ float4 g_V4 [(size_t)MTOT * C_DIM / 4];
__device__ float  g_S  [(size_t)MTOT * 16];
__device__ float4 g_pq4[NB * C_DIM / 4];
__device__ float4 g_pk4[NB * C_DIM / 4];
__device__ uint4  g_A1h[(size_t)MTOT * C_DIM / 8];
__device__ uint4  g_A1l[(size_t)MTOT * C_DIM / 8];
__device__ uint4  g_A2h[(size_t)MTOT * C_DIM / 8];
__device__ uint4  g_A2l[(size_t)MTOT * C_DIM / 8];
__device__ uint4  g_Wh [(size_t)C_DIM * C_DIM / 8];
__device__ uint4  g_Wl [(size_t)C_DIM * C_DIM / 8];

// ---------------- PTX helpers (sm_80-level only, no tcgen05) ---------------
__device__ __forceinline__ uint32_t smem_u32(const void* p) {
    uint32_t a;
    asm("{ .reg .u64 t; cvta.to.shared.u64 t, %1; cvt.u32.u64 %0, t; }" : "=r"(a) : "l"(p));
    return a;
}
__device__ __forceinline__ void cp16(uint32_t dst, const void* src) {
    asm volatile("cp.async.cg.shared.global [%0], [%1], 16;" :: "r"(dst), "l"(src));
}
#define CP_COMMIT() asm volatile("cp.async.commit_group;" ::: "memory")
#define CP_WAIT(n)  asm volatile("cp.async.wait_group %0;" :: "n"(n) : "memory")

#define LDSM4(r, a) \
    asm volatile("ldmatrix.sync.aligned.m8n8.x4.shared.b16 {%0,%1,%2,%3}, [%4];" \
        : "=r"((r)[0]), "=r"((r)[1]), "=r"((r)[2]), "=r"((r)[3]) : "r"(a))

#define MMA16(d, a, b0, b1) \
    asm volatile("mma.sync.aligned.m16n8k16.row.col.f32.bf16.bf16.f32 " \
        "{%0,%1,%2,%3}, {%4,%5,%6,%7}, {%8,%9}, {%0,%1,%2,%3};" \
        : "+f"((d)[0]), "+f"((d)[1]), "+f"((d)[2]), "+f"((d)[3]) \
        : "r"((a)[0]), "r"((a)[1]), "r"((a)[2]), "r"((a)[3]), "r"(b0), "r"(b1))

// ---------------------------------------------------------------------------
// One K-chunk: A tile [128 x 64 bf16] hi/lo + B tile [128 x 64 bf16] hi/lo,
// each row = 128B, SW128 swizzle (off ^ ((off>>3)&0x70)).
// ---------------------------------------------------------------------------
__device__ __forceinline__ void load_chunk(
    uint32_t sb,
    const __nv_bfloat16* __restrict__ Ah, const __nv_bfloat16* __restrict__ Al,
    const __nv_bfloat16* __restrict__ Bh, const __nv_bfloat16* __restrict__ Bl,
    int m0, int n0, int k0, int tid)
{
    const size_t kbyte = (size_t)k0 * 2;
    #pragma unroll
    for (int j = 0; j < 4; j++) {
        const int c = tid + j * 256;
        const int r = c >> 3, col = (c & 7) << 4;
        const uint32_t off = r * 128 + col;
        const uint32_t sw = off ^ ((off >> 3) & 0x70);
        const size_t goA = ((size_t)(m0 + r) << 11) + kbyte + col;
        const size_t goB = ((size_t)(n0 + r) << 11) + kbyte + col;
        cp16(sb + sw,         (const char*)Ah + goA);
        cp16(sb + 16384 + sw, (const char*)Al + goA);
        cp16(sb + 32768 + sw, (const char*)Bh + goB);
        cp16(sb + 49152 + sw, (const char*)Bl + goB);
    }
}

// ---------------------------------------------------------------------------
// bf16x3 GEMM via mma.sync: C = (Ah+Al) @ (Bh+Bl)^T + bias, B stored [n][k].
// EPI 0: fp32 C.  EPI 1: bf16 hi/lo split of (acc + bias + resid).
// ---------------------------------------------------------------------------
template <int EPI>
__global__ __launch_bounds__(256, 1)
void gemm_mma(const __nv_bfloat16* __restrict__ Ah, const __nv_bfloat16* __restrict__ Al,
              const __nv_bfloat16* __restrict__ Bh, const __nv_bfloat16* __restrict__ Bl,
              const float* __restrict__ bias, float* __restrict__ Cf,
              __nv_bfloat16* __restrict__ Oh, __nv_bfloat16* __restrict__ Ol,
              const float* __restrict__ resid)
{
    extern __shared__ char dsm[];
    const uint32_t tiles = (smem_u32(dsm) + 1023u) & ~1023u;
    const int tid  = threadIdx.x;
    const int lane = tid & 31;
    const int w    = tid >> 5;
    const int m0   = blockIdx.y * BM;
    const int n0   = blockIdx.x * BN;
    const int warp_m = (w >> 2) * 64;    // 0 or 64
    const int warp_n = (w & 3) * 32;     // 0,32,64,96

    // ldmatrix per-lane addressing components
    const int row16 = (lane & 7) | (((lane >> 3) & 1) << 3);   // 0..15
    const int kcl   = lane >> 4;                               // 0/1 (k-chunk)
    const int rA = warp_m + row16;
    const int rB = warp_n + row16;
    const uint32_t swA = (uint32_t)(rA & 7);
    const uint32_t swB = (uint32_t)(rB & 7);

    float acc[4][4][4];
    #pragma unroll
    for (int i = 0; i < 4; i++)
        #pragma unroll
        for (int j = 0; j < 4; j++)
            #pragma unroll
            for (int q = 0; q < 4; q++) acc[i][j][q] = 0.f;

    load_chunk(tiles, Ah, Al, Bh, Bl, m0, n0, 0, tid);
    CP_COMMIT();

    for (int i = 0; i < NCHUNK; i++) {
        const int s = i & 1;
        const uint32_t sb = tiles + (uint32_t)s * STAGE_BYTES;
        if (i + 1 < NCHUNK) {
            load_chunk(tiles + (uint32_t)(s ^ 1) * STAGE_BYTES,
                       Ah, Al, Bh, Bl, m0, n0, (i + 1) * KC, tid);
            CP_COMMIT();
            CP_WAIT(1);
        } else {
            CP_WAIT(0);
        }
        __syncthreads();

        const uint32_t aBaseH = sb           + (uint32_t)rA * 128;
        const uint32_t aBaseL = sb + 16384u  + (uint32_t)rA * 128;
        const uint32_t bBaseH = sb + 32768u  + (uint32_t)rB * 128;
        const uint32_t bBaseL = sb + 49152u  + (uint32_t)rB * 128;

        #pragma unroll
        for (int ks = 0; ks < 4; ks++) {
            const uint32_t aoff = (uint32_t)(((ks * 2 + kcl) ^ swA) << 4);
            const uint32_t boff = (uint32_t)(((ks * 2 + kcl) ^ swB) << 4);

            uint32_t af[4][4], bh[2][4], bl[2][4];
            #pragma unroll
            for (int mf = 0; mf < 4; mf++) LDSM4(af[mf], aBaseH + mf * 2048u + aoff);
            #pragma unroll
            for (int nb = 0; nb < 2; nb++) LDSM4(bh[nb], bBaseH + nb * 2048u + boff);
            #pragma unroll
            for (int nb = 0; nb < 2; nb++) LDSM4(bl[nb], bBaseL + nb * 2048u + boff);

            // product 1: Ah * Bh ; product 2: Ah * Bl
            #pragma unroll
            for (int mf = 0; mf < 4; mf++)
                #pragma unroll
                for (int nf = 0; nf < 4; nf++) {
                    const int nb = nf >> 1, sel = nf & 1;
                    MMA16(acc[mf][nf], af[mf], bh[nb][sel], bh[nb][sel + 2]);
                    MMA16(acc[mf][nf], af[mf], bl[nb][sel], bl[nb][sel + 2]);
                }
            // product 3: Al * Bh (overwrite af)
            #pragma unroll
            for (int mf = 0; mf < 4; mf++) LDSM4(af[mf], aBaseL + mf * 2048u + aoff);
            #pragma unroll
            for (int mf = 0; mf < 4; mf++)
                #pragma unroll
                for (int nf = 0; nf < 4; nf++) {
                    const int nb = nf >> 1, sel = nf & 1;
                    MMA16(acc[mf][nf], af[mf], bh[nb][sel], bh[nb][sel + 2]);
                }
        }
        __syncthreads();
    }

    // ---------------- epilogue ----------------
    const int tr = lane >> 2;            // 0..7
    const int tc = (lane & 3) * 2;       // 0,2,4,6
    #pragma unroll
    for (int nf = 0; nf < 4; nf++) {
        const int col = n0 + warp_n + nf * 8 + tc;
        const float b0 = bias[col], b1 = bias[col + 1];
        #pragma unroll
        for (int mf = 0; mf < 4; mf++) {
            #pragma unroll
            for (int half = 0; half < 2; half++) {
                const int row = m0 + warp_m + mf * 16 + tr + half * 8;
                float v0 = acc[mf][nf][half * 2 + 0] + b0;
                float v1 = acc[mf][nf][half * 2 + 1] + b1;
                if (EPI == 0) {
                    *(float2*)(Cf + (size_t)row * C_DIM + col) = make_float2(v0, v1);
                } else {
                    const float2 r2 = *(const float2*)(resid + (size_t)row * C_DIM + col);
                    v0 += r2.x; v1 += r2.y;
                    const __nv_bfloat16 h0 = __float2bfloat16(v0);
                    const __nv_bfloat16 h1 = __float2bfloat16(v1);
                    const __nv_bfloat16 l0 = __float2bfloat16(v0 - __bfloat162float(h0));
                    const __nv_bfloat16 l1 = __float2bfloat16(v1 - __bfloat162float(h1));
                    __nv_bfloat162 hp; hp.x = h0; hp.y = h1;
                    __nv_bfloat162 lp; lp.x = l0; lp.y = l1;
                    *(__nv_bfloat162*)(Oh + (size_t)row * C_DIM + col) = hp;
                    *(__nv_bfloat162*)(Ol + (size_t)row * C_DIM + col) = lp;
                }
            }
        }
    }
}

// ---------------- activation split (optional gate) -------------------------
template <int GATE>
__global__ __launch_bounds__(256)
void convA_kernel(const float* __restrict__ X, const float* __restrict__ gate,
                  __nv_bfloat16* __restrict__ Ah, __nv_bfloat16* __restrict__ Al)
{
    const size_t e = ((size_t)blockIdx.x * 256 + threadIdx.x) * 8;
    float v[8];
    *(float4*)(v)     = *(const float4*)(X + e);
    *(float4*)(v + 4) = *(const float4*)(X + e + 4);
    if (GATE) {
        const size_t c = e & (C_DIM - 1);
        const size_t bat = e >> 22;
        float g[8];
        *(float4*)(g)     = *(const float4*)(gate + bat * C_DIM + c);
        *(float4*)(g + 4) = *(const float4*)(gate + bat * C_DIM + c + 4);
        #pragma unroll
        for (int j = 0; j < 8; j++) v[j] *= g[j];
    }
    __nv_bfloat16 hb[8], lb[8];
    #pragma unroll
    for (int j = 0; j < 8; j++) {
        __nv_bfloat16 h = __float2bfloat16(v[j]);
        hb[j] = h;
        lb[j] = __float2bfloat16(v[j] - __bfloat162float(h));
    }
    *(uint4*)(Ah + e) = *(uint4*)hb;
    *(uint4*)(Al + e) = *(uint4*)lb;
}

// ---------------- weight transpose + split: W[k][n] -> Wh/Wl[n][k] ---------
__global__ __launch_bounds__(256)
void convW_kernel(const float* __restrict__ W,
                  __nv_bfloat16* __restrict__ Wh, __nv_bfloat16* __restrict__ Wl)
{
    __shared__ float t[32][33];
    const int bx = blockIdx.x & 31, by = blockIdx.x >> 5;
    const int x = threadIdx.x & 31, y = threadIdx.x >> 5;
    #pragma unroll
    for (int j = 0; j < 4; j++)
        t[y + j * 8][x] = W[(size_t)(by * 32 + y + j * 8) * C_DIM + bx * 32 + x];
    __syncthreads();
    #pragma unroll
    for (int j = 0; j < 4; j++) {
        const float v = t[x][y + j * 8];
        const __nv_bfloat16 h = __float2bfloat16(v);
        const size_t o = (size_t)(bx * 32 + y + j * 8) * C_DIM + by * 32 + x;
        Wh[o] = h;
        Wl[o] = __float2bfloat16(v - __bfloat162float(h));
    }
}

// ---------------- logits: 4 rows per warp ----------------------------------
template <bool GATE>
__global__ __launch_bounds__(256)
void logits_kernel(const float* __restrict__ X, const float* __restrict__ W,
                   const float* __restrict__ b, const float* __restrict__ gate,
                   float* __restrict__ S)
{
    const int warp = threadIdx.x >> 5, lane = threadIdx.x & 31;
    const int r0 = blockIdx.x * 32 + warp * 4;
    const int bat = r0 >> 12;
    const float* gp = GATE ? (gate + (size_t)bat * C_DIM) : nullptr;

    float acc[4][16];
    #pragma unroll
    for (int r = 0; r < 4; r++)
        #pragma unroll
        for (int h = 0; h < 16; h++) acc[r][h] = 0.f;

    for (int c = lane; c < C_DIM; c += 32) {
        float a[4];
        #pragma unroll
        for (int r = 0; r < 4; r++) a[r] = X[(size_t)(r0 + r) * C_DIM + c];
        if (GATE) {
            const float g = gp[c];
            #pragma unroll
            for (int r = 0; r < 4; r++) a[r] *= g;
        }
        const float4* wp = (const float4*)(W + (size_t)c * 16);
        const float4 w0 = wp[0], w1 = wp[1], w2 = wp[2], w3 = wp[3];
        const float wv[16] = { w0.x, w0.y, w0.z, w0.w, w1.x, w1.y, w1.z, w1.w,
                               w2.x, w2.y, w2.z, w2.w, w3.x, w3.y, w3.z, w3.w };
        #pragma unroll
        for (int r = 0; r < 4; r++)
            #pragma unroll
            for (int h = 0; h < 16; h++) acc[r][h] += a[r] * wv[h];
    }
    #pragma unroll
    for (int r = 0; r < 4; r++)
        #pragma unroll
        for (int h = 0; h < 16; h++)
            #pragma unroll
            for (int off = 16; off; off >>= 1)
                acc[r][h] += __shfl_xor_sync(0xffffffffu, acc[r][h], off);
    if (lane == 0) {
        const float scale = 0.125f;
        #pragma unroll
        for (int r = 0; r < 4; r++)
            #pragma unroll
            for (int h = 0; h < 16; h++)
                S[(size_t)(r0 + r) * 16 + h] = (acc[r][h] + b[h]) * scale;
    }
}

// ---------------- softmax over L + pooling ---------------------------------
__global__ __launch_bounds__(512)
void softpool_kernel(const float* __restrict__ S, const float* __restrict__ X,
                     float* __restrict__ pooled)
{
    __shared__ float red[512];
    const int nh = blockIdx.x, n = nh >> 4, h = nh & 15;
    const int tid = threadIdx.x;
    const float* sp = S + (size_t)n * LSEQ * 16 + h;

    float m = -1e30f;
    for (int l = tid; l < LSEQ; l += 512) m = fmaxf(m, sp[(size_t)l * 16]);
    red[tid] = m; __syncthreads();
    for (int s = 256; s; s >>= 1) { if (tid < s) red[tid] = fmaxf(red[tid], red[tid + s]); __syncthreads(); }
    m = red[0]; __syncthreads();

    float sum = 0.f;
    for (int l = tid; l < LSEQ; l += 512) sum += __expf(sp[(size_t)l * 16] - m);
    red[tid] = sum; __syncthreads();
    for (int s = 256; s; s >>= 1) { if (tid < s) red[tid] += red[tid + s]; __syncthreads(); }
    const float invZ = 1.f / red[0]; __syncthreads();

    const int d = tid & 63, lg = tid >> 6;
    const float* xp = X + (size_t)n * LSEQ * C_DIM + h * 64 + d;
    float acc = 0.f;
    for (int l = lg; l < LSEQ; l += 8) {
        float wgt = __expf(sp[(size_t)l * 16] - m) * invZ;
        acc += wgt * xp[(size_t)l * C_DIM];
    }
    red[tid] = acc; __syncthreads();
    if (tid < 64) {
        float s = 0.f;
        #pragma unroll
        for (int g = 0; g < 8; g++) s += red[g * 64 + d];
        pooled[(size_t)n * C_DIM + h * 64 + d] = s;
    }
}

// ---------------------------------------------------------------------------
extern "C" void kernel_launch(void* const* d_in, const int* in_sizes, int n_in,
                              void* d_out, int out_size)
{
    const float* x_q  = (const float*)d_in[0];
    const float* x_kv = (const float*)d_in[1];
    const float* Wq   = (const float*)d_in[2];
    const float* bq   = (const float*)d_in[3];
    const float* Wqa  = (const float*)d_in[4];
    const float* bqa  = (const float*)d_in[5];
    const float* Wk   = (const float*)d_in[6];
    const float* bk   = (const float*)d_in[7];
    const float* Wka  = (const float*)d_in[8];
    const float* bka  = (const float*)d_in[9];
    const float* Wv   = (const float*)d_in[10];
    const float* bv   = (const float*)d_in[11];
    const float* Wt   = (const float*)d_in[12];
    const float* bt   = (const float*)d_in[13];
    const float* Wp   = (const float*)d_in[14];
    const float* bp   = (const float*)d_in[15];
    float* out = (float*)d_out;

    float *Q, *K, *V, *S, *pq, *pk;
    __nv_bfloat16 *A1h, *A1l, *A2h, *A2l, *Wh, *Wl;
    cudaGetSymbolAddress((void**)&Q,   g_Q4);
    cudaGetSymbolAddress((void**)&K,   g_K4);
    cudaGetSymbolAddress((void**)&V,   g_V4);
    cudaGetSymbolAddress((void**)&S,   g_S);
    cudaGetSymbolAddress((void**)&pq,  g_pq4);
    cudaGetSymbolAddress((void**)&pk,  g_pk4);
    cudaGetSymbolAddress((void**)&A1h, g_A1h);
    cudaGetSymbolAddress((void**)&A1l, g_A1l);
    cudaGetSymbolAddress((void**)&A2h, g_A2h);
    cudaGetSymbolAddress((void**)&A2l, g_A2l);
    cudaGetSymbolAddress((void**)&Wh,  g_Wh);
    cudaGetSymbolAddress((void**)&Wl,  g_Wl);

    cudaFuncSetAttribute(gemm_mma<0>, cudaFuncAttributeMaxDynamicSharedMemorySize, DSMEM);
    cudaFuncSetAttribute(gemm_mma<1>, cudaFuncAttributeMaxDynamicSharedMemorySize, DSMEM);

    const dim3 gg(C_DIM / BN, MTOT / BM);                    // (8, 256)
    const int convAg = (int)((size_t)MTOT * C_DIM / 2048);   // 16384

    // 1: Q = x_q @ Wq + bq
    convW_kernel<<<1024, 256>>>(Wq, Wh, Wl);
    convA_kernel<0><<<convAg, 256>>>(x_q, nullptr, A1h, A1l);
    gemm_mma<0><<<gg, 256, DSMEM>>>(A1h, A1l, Wh, Wl, bq, Q, nullptr, nullptr, nullptr);

    // query pooling
    logits_kernel<false><<<MTOT / 32, 256>>>(Q, Wqa, bqa, nullptr, S);
    softpool_kernel<<<NB * 16, 512>>>(S, Q, pq);

    // 2: K = x_kv @ Wk + bk
    convW_kernel<<<1024, 256>>>(Wk, Wh, Wl);
    convA_kernel<0><<<convAg, 256>>>(x_kv, nullptr, A2h, A2l);
    gemm_mma<0><<<gg, 256, DSMEM>>>(A2h, A2l, Wh, Wl, bk, K, nullptr, nullptr, nullptr);

    // gated key pooling
    logits_kernel<true><<<MTOT / 32, 256>>>(K, Wka, bka, pq, S);
    softpool_kernel<<<NB * 16, 512>>>(S, K, pk);

    // 3: V = x_kv @ Wv + bv  (reuse x_kv split)
    convW_kernel<<<1024, 256>>>(Wv, Wh, Wl);
    gemm_mma<0><<<gg, 256, DSMEM>>>(A2h, A2l, Wh, Wl, bv, V, nullptr, nullptr, nullptr);

    // 4: T+Q = (V*pk) @ Wt + bt + Q  -> bf16 split into A2 buffers
    convA_kernel<1><<<convAg, 256>>>(V, pk, A1h, A1l);
    convW_kernel<<<1024, 256>>>(Wt, Wh, Wl);
    gemm_mma<1><<<gg, 256, DSMEM>>>(A1h, A1l, Wh, Wl, bt, nullptr, A2h, A2l, Q);

    // 5: out = (T+Q) @ Wp + bp
    convW_kernel<<<1024, 256>>>(Wp, Wh, Wl);
    gemm_mma<0><<<gg, 256, DSMEM>>>(A2h, A2l, Wh, Wl, bp, out, nullptr, nullptr, nullptr);
}

// round 12
// speedup vs baseline: 2.5626x; 1.0161x over previous
#include <cuda_runtime.h>
#include <cuda_bf16.h>
#include <cstdint>

#define C_DIM 1024
#define NB 8
#define LSEQ 4096
#define MTOT (NB * LSEQ)   // 32768
#define BM 128
#define BN 128
#define KC 64
#define NCHUNK (C_DIM / KC)          // 16
#define STAGE_BYTES (64 * 1024)      // Ah 16K | Al 16K | Bh 16K | Bl 16K
#define DSMEM (1024 + 2 * STAGE_BYTES)

// ---------------- scratch --------------------------------------------------
__device__ float4 g_Q4 [(size_t)MTOT * C_DIM / 4];
__device__ float4 g_K4 [(size_t)MTOT * C_DIM / 4];
__device__ float  g_S  [(size_t)MTOT * 16];
__device__ float4 g_pq4[NB * C_DIM / 4];
__device__ float4 g_pk4[NB * C_DIM / 4];
__device__ uint4  g_A1h[(size_t)MTOT * C_DIM / 8];
__device__ uint4  g_A1l[(size_t)MTOT * C_DIM / 8];
__device__ uint4  g_A2h[(size_t)MTOT * C_DIM / 8];
__device__ uint4  g_A2l[(size_t)MTOT * C_DIM / 8];
__device__ uint4  g_Wh [(size_t)C_DIM * C_DIM / 8];
__device__ uint4  g_Wl [(size_t)C_DIM * C_DIM / 8];

// ---------------- PTX helpers (sm_80-level only) ----------------------------
__device__ __forceinline__ uint32_t smem_u32(const void* p) {
    uint32_t a;
    asm("{ .reg .u64 t; cvta.to.shared.u64 t, %1; cvt.u32.u64 %0, t; }" : "=r"(a) : "l"(p));
    return a;
}
__device__ __forceinline__ void cp16(uint32_t dst, const void* src) {
    asm volatile("cp.async.cg.shared.global [%0], [%1], 16;" :: "r"(dst), "l"(src));
}
#define CP_COMMIT() asm volatile("cp.async.commit_group;" ::: "memory")
#define CP_WAIT(n)  asm volatile("cp.async.wait_group %0;" :: "n"(n) : "memory")

#define LDSM4(r, a) \
    asm volatile("ldmatrix.sync.aligned.m8n8.x4.shared.b16 {%0,%1,%2,%3}, [%4];" \
        : "=r"((r)[0]), "=r"((r)[1]), "=r"((r)[2]), "=r"((r)[3]) : "r"(a))

#define MMA16(d, a, b0, b1) \
    asm volatile("mma.sync.aligned.m16n8k16.row.col.f32.bf16.bf16.f32 " \
        "{%0,%1,%2,%3}, {%4,%5,%6,%7}, {%8,%9}, {%0,%1,%2,%3};" \
        : "+f"((d)[0]), "+f"((d)[1]), "+f"((d)[2]), "+f"((d)[3]) \
        : "r"((a)[0]), "r"((a)[1]), "r"((a)[2]), "r"((a)[3]), "r"(b0), "r"(b1))

// ---------------------------------------------------------------------------
// One K-chunk: A tile [128 x 64 bf16] hi/lo + B tile [128 x 64 bf16] hi/lo,
// each row = 128B, SW128 swizzle.
// ---------------------------------------------------------------------------
__device__ __forceinline__ void load_chunk(
    uint32_t sb,
    const __nv_bfloat16* __restrict__ Ah, const __nv_bfloat16* __restrict__ Al,
    const __nv_bfloat16* __restrict__ Bh, const __nv_bfloat16* __restrict__ Bl,
    int m0, int n0, int k0, int tid)
{
    const size_t kbyte = (size_t)k0 * 2;
    #pragma unroll
    for (int j = 0; j < 4; j++) {
        const int c = tid + j * 256;
        const int r = c >> 3, col = (c & 7) << 4;
        const uint32_t off = r * 128 + col;
        const uint32_t sw = off ^ ((off >> 3) & 0x70);
        const size_t goA = ((size_t)(m0 + r) << 11) + kbyte + col;
        const size_t goB = ((size_t)(n0 + r) << 11) + kbyte + col;
        cp16(sb + sw,         (const char*)Ah + goA);
        cp16(sb + 16384 + sw, (const char*)Al + goA);
        cp16(sb + 32768 + sw, (const char*)Bh + goB);
        cp16(sb + 49152 + sw, (const char*)Bl + goB);
    }
}

// ---------------------------------------------------------------------------
// bf16x3 GEMM via mma.sync: C = (Ah+Al) @ (Bh+Bl)^T + bias, B stored [n][k].
// EPI 0: fp32 C.
// EPI 1: bf16 hi/lo split of (acc + bias + resid[row,col]).
// EPI 2: bf16 hi/lo split of (acc + bias) * gate[batch,col]   (resid = gate).
// Three products are issued as separate sweeps so each accumulator is only
// revisited every 16 MMAs (hides HMMA latency on 2 warps/SMSP).
// ---------------------------------------------------------------------------
template <int EPI>
__global__ __launch_bounds__(256, 1)
void gemm_mma(const __nv_bfloat16* __restrict__ Ah, const __nv_bfloat16* __restrict__ Al,
              const __nv_bfloat16* __restrict__ Bh, const __nv_bfloat16* __restrict__ Bl,
              const float* __restrict__ bias, float* __restrict__ Cf,
              __nv_bfloat16* __restrict__ Oh, __nv_bfloat16* __restrict__ Ol,
              const float* __restrict__ resid)
{
    extern __shared__ char dsm[];
    const uint32_t tiles = (smem_u32(dsm) + 1023u) & ~1023u;
    const int tid  = threadIdx.x;
    const int lane = tid & 31;
    const int w    = tid >> 5;
    const int m0   = blockIdx.y * BM;
    const int n0   = blockIdx.x * BN;
    const int warp_m = (w >> 2) * 64;    // 0 or 64
    const int warp_n = (w & 3) * 32;     // 0,32,64,96

    const int row16 = (lane & 7) | (((lane >> 3) & 1) << 3);
    const int kcl   = lane >> 4;
    const int rA = warp_m + row16;
    const int rB = warp_n + row16;
    const uint32_t swA = (uint32_t)(rA & 7);
    const uint32_t swB = (uint32_t)(rB & 7);

    float acc[4][4][4];
    #pragma unroll
    for (int i = 0; i < 4; i++)
        #pragma unroll
        for (int j = 0; j < 4; j++)
            #pragma unroll
            for (int q = 0; q < 4; q++) acc[i][j][q] = 0.f;

    load_chunk(tiles, Ah, Al, Bh, Bl, m0, n0, 0, tid);
    CP_COMMIT();

    for (int i = 0; i < NCHUNK; i++) {
        const int s = i & 1;
        const uint32_t sb = tiles + (uint32_t)s * STAGE_BYTES;
        if (i + 1 < NCHUNK) {
            load_chunk(tiles + (uint32_t)(s ^ 1) * STAGE_BYTES,
                       Ah, Al, Bh, Bl, m0, n0, (i + 1) * KC, tid);
            CP_COMMIT();
            CP_WAIT(1);
        } else {
            CP_WAIT(0);
        }
        __syncthreads();

        const uint32_t aBaseH = sb           + (uint32_t)rA * 128;
        const uint32_t aBaseL = sb + 16384u  + (uint32_t)rA * 128;
        const uint32_t bBaseH = sb + 32768u  + (uint32_t)rB * 128;
        const uint32_t bBaseL = sb + 49152u  + (uint32_t)rB * 128;

        #pragma unroll
        for (int ks = 0; ks < 4; ks++) {
            const uint32_t aoff = (uint32_t)(((ks * 2 + kcl) ^ swA) << 4);
            const uint32_t boff = (uint32_t)(((ks * 2 + kcl) ^ swB) << 4);

            uint32_t ahf[4][4], alf[4][4], bhf[2][4], blf[2][4];
            #pragma unroll
            for (int mf = 0; mf < 4; mf++) LDSM4(ahf[mf], aBaseH + mf * 2048u + aoff);
            #pragma unroll
            for (int nb = 0; nb < 2; nb++) LDSM4(bhf[nb], bBaseH + nb * 2048u + boff);
            #pragma unroll
            for (int mf = 0; mf < 4; mf++) LDSM4(alf[mf], aBaseL + mf * 2048u + aoff);
            #pragma unroll
            for (int nb = 0; nb < 2; nb++) LDSM4(blf[nb], bBaseL + nb * 2048u + boff);

            // sweep 1: Ah * Bh
            #pragma unroll
            for (int mf = 0; mf < 4; mf++)
                #pragma unroll
                for (int nf = 0; nf < 4; nf++) {
                    const int nb = nf >> 1, sel = nf & 1;
                    MMA16(acc[mf][nf], ahf[mf], bhf[nb][sel], bhf[nb][sel + 2]);
                }
            // sweep 2: Al * Bh
            #pragma unroll
            for (int mf = 0; mf < 4; mf++)
                #pragma unroll
                for (int nf = 0; nf < 4; nf++) {
                    const int nb = nf >> 1, sel = nf & 1;
                    MMA16(acc[mf][nf], alf[mf], bhf[nb][sel], bhf[nb][sel + 2]);
                }
            // sweep 3: Ah * Bl
            #pragma unroll
            for (int mf = 0; mf < 4; mf++)
                #pragma unroll
                for (int nf = 0; nf < 4; nf++) {
                    const int nb = nf >> 1, sel = nf & 1;
                    MMA16(acc[mf][nf], ahf[mf], blf[nb][sel], blf[nb][sel + 2]);
                }
        }
        __syncthreads();
    }

    // ---------------- epilogue ----------------
    const int tr = lane >> 2;
    const int tc = (lane & 3) * 2;
    const int bat = m0 / LSEQ;
    const float* gp = (EPI == 2) ? (resid + (size_t)bat * C_DIM) : nullptr;

    #pragma unroll
    for (int nf = 0; nf < 4; nf++) {
        const int col = n0 + warp_n + nf * 8 + tc;
        const float b0 = bias[col], b1 = bias[col + 1];
        float g0 = 1.f, g1 = 1.f;
        if (EPI == 2) { g0 = gp[col]; g1 = gp[col + 1]; }
        #pragma unroll
        for (int mf = 0; mf < 4; mf++) {
            #pragma unroll
            for (int half = 0; half < 2; half++) {
                const int row = m0 + warp_m + mf * 16 + tr + half * 8;
                float v0 = acc[mf][nf][half * 2 + 0] + b0;
                float v1 = acc[mf][nf][half * 2 + 1] + b1;
                if (EPI == 0) {
                    *(float2*)(Cf + (size_t)row * C_DIM + col) = make_float2(v0, v1);
                } else {
                    if (EPI == 1) {
                        const float2 r2 = *(const float2*)(resid + (size_t)row * C_DIM + col);
                        v0 += r2.x; v1 += r2.y;
                    } else {
                        v0 *= g0; v1 *= g1;
                    }
                    const __nv_bfloat16 h0 = __float2bfloat16(v0);
                    const __nv_bfloat16 h1 = __float2bfloat16(v1);
                    const __nv_bfloat16 l0 = __float2bfloat16(v0 - __bfloat162float(h0));
                    const __nv_bfloat16 l1 = __float2bfloat16(v1 - __bfloat162float(h1));
                    __nv_bfloat162 hp; hp.x = h0; hp.y = h1;
                    __nv_bfloat162 lp; lp.x = l0; lp.y = l1;
                    *(__nv_bfloat162*)(Oh + (size_t)row * C_DIM + col) = hp;
                    *(__nv_bfloat162*)(Ol + (size_t)row * C_DIM + col) = lp;
                }
            }
        }
    }
}

// ---------------- activation split ------------------------------------------
__global__ __launch_bounds__(256)
void convA_kernel(const float* __restrict__ X,
                  __nv_bfloat16* __restrict__ Ah, __nv_bfloat16* __restrict__ Al)
{
    const size_t e = ((size_t)blockIdx.x * 256 + threadIdx.x) * 8;
    float v[8];
    *(float4*)(v)     = *(const float4*)(X + e);
    *(float4*)(v + 4) = *(const float4*)(X + e + 4);
    __nv_bfloat16 hb[8], lb[8];
    #pragma unroll
    for (int j = 0; j < 8; j++) {
        __nv_bfloat16 h = __float2bfloat16(v[j]);
        hb[j] = h;
        lb[j] = __float2bfloat16(v[j] - __bfloat162float(h));
    }
    *(uint4*)(Ah + e) = *(uint4*)hb;
    *(uint4*)(Al + e) = *(uint4*)lb;
}

// ---------------- weight transpose + split: W[k][n] -> Wh/Wl[n][k] ----------
__global__ __launch_bounds__(256)
void convW_kernel(const float* __restrict__ W,
                  __nv_bfloat16* __restrict__ Wh, __nv_bfloat16* __restrict__ Wl)
{
    __shared__ float t[32][33];
    const int bx = blockIdx.x & 31, by = blockIdx.x >> 5;
    const int x = threadIdx.x & 31, y = threadIdx.x >> 5;
    #pragma unroll
    for (int j = 0; j < 4; j++)
        t[y + j * 8][x] = W[(size_t)(by * 32 + y + j * 8) * C_DIM + bx * 32 + x];
    __syncthreads();
    #pragma unroll
    for (int j = 0; j < 4; j++) {
        const float v = t[x][y + j * 8];
        const __nv_bfloat16 h = __float2bfloat16(v);
        const size_t o = (size_t)(bx * 32 + y + j * 8) * C_DIM + by * 32 + x;
        Wh[o] = h;
        Wl[o] = __float2bfloat16(v - __bfloat162float(h));
    }
}

// ---------------- logits: 4 rows per warp, float4 X loads -------------------
template <bool GATE>
__global__ __launch_bounds__(256)
void logits_kernel(const float* __restrict__ X, const float* __restrict__ W,
                   const float* __restrict__ b, const float* __restrict__ gate,
                   float* __restrict__ S)
{
    const int warp = threadIdx.x >> 5, lane = threadIdx.x & 31;
    const int r0 = blockIdx.x * 32 + warp * 4;
    const int bat = r0 >> 12;
    const float* gp = GATE ? (gate + (size_t)bat * C_DIM) : nullptr;

    float acc[4][16];
    #pragma unroll
    for (int r = 0; r < 4; r++)
        #pragma unroll
        for (int h = 0; h < 16; h++) acc[r][h] = 0.f;

    #pragma unroll 2
    for (int it = 0; it < C_DIM / 128; it++) {
        const int c = it * 128 + lane * 4;
        float4 a4[4];
        #pragma unroll
        for (int r = 0; r < 4; r++)
            a4[r] = *(const float4*)(X + (size_t)(r0 + r) * C_DIM + c);
        if (GATE) {
            const float4 g4 = *(const float4*)(gp + c);
            #pragma unroll
            for (int r = 0; r < 4; r++) {
                a4[r].x *= g4.x; a4[r].y *= g4.y; a4[r].z *= g4.z; a4[r].w *= g4.w;
            }
        }
        #pragma unroll
        for (int q = 0; q < 4; q++) {
            const float4* wp = (const float4*)(W + (size_t)(c + q) * 16);
            const float4 w0 = wp[0], w1 = wp[1], w2 = wp[2], w3 = wp[3];
            const float wv[16] = { w0.x, w0.y, w0.z, w0.w, w1.x, w1.y, w1.z, w1.w,
                                   w2.x, w2.y, w2.z, w2.w, w3.x, w3.y, w3.z, w3.w };
            #pragma unroll
            for (int r = 0; r < 4; r++) {
                const float a = (q == 0) ? a4[r].x : (q == 1) ? a4[r].y
                              : (q == 2) ? a4[r].z : a4[r].w;
                #pragma unroll
                for (int h = 0; h < 16; h++) acc[r][h] += a * wv[h];
            }
        }
    }
    #pragma unroll
    for (int r = 0; r < 4; r++)
        #pragma unroll
        for (int h = 0; h < 16; h++)
            #pragma unroll
            for (int off = 16; off; off >>= 1)
                acc[r][h] += __shfl_xor_sync(0xffffffffu, acc[r][h], off);
    if (lane == 0) {
        const float scale = 0.125f;
        #pragma unroll
        for (int r = 0; r < 4; r++)
            #pragma unroll
            for (int h = 0; h < 16; h++)
                S[(size_t)(r0 + r) * 16 + h] = (acc[r][h] + b[h]) * scale;
    }
}

// ---------------- softmax over L + pooling ----------------------------------
__global__ __launch_bounds__(1024)
void softpool_kernel(const float* __restrict__ S, const float* __restrict__ X,
                     float* __restrict__ pooled)
{
    __shared__ float red[1024];
    const int nh = blockIdx.x, n = nh >> 4, h = nh & 15;
    const int tid = threadIdx.x;
    const float* sp = S + (size_t)n * LSEQ * 16 + h;

    float m = -1e30f;
    for (int l = tid; l < LSEQ; l += 1024) m = fmaxf(m, sp[(size_t)l * 16]);
    red[tid] = m; __syncthreads();
    for (int s = 512; s; s >>= 1) { if (tid < s) red[tid] = fmaxf(red[tid], red[tid + s]); __syncthreads(); }
    m = red[0]; __syncthreads();

    float sum = 0.f;
    for (int l = tid; l < LSEQ; l += 1024) sum += __expf(sp[(size_t)l * 16] - m);
    red[tid] = sum; __syncthreads();
    for (int s = 512; s; s >>= 1) { if (tid < s) red[tid] += red[tid + s]; __syncthreads(); }
    const float invZ = 1.f / red[0]; __syncthreads();

    const int d = tid & 63, lg = tid >> 6;   // 16 l-groups
    const float* xp = X + (size_t)n * LSEQ * C_DIM + h * 64 + d;
    float acc = 0.f;
    for (int l = lg; l < LSEQ; l += 16) {
        float wgt = __expf(sp[(size_t)l * 16] - m) * invZ;
        acc += wgt * xp[(size_t)l * C_DIM];
    }
    red[tid] = acc; __syncthreads();
    if (tid < 64) {
        float s = 0.f;
        #pragma unroll
        for (int g = 0; g < 16; g++) s += red[g * 64 + d];
        pooled[(size_t)n * C_DIM + h * 64 + d] = s;
    }
}

// ---------------------------------------------------------------------------
extern "C" void kernel_launch(void* const* d_in, const int* in_sizes, int n_in,
                              void* d_out, int out_size)
{
    const float* x_q  = (const float*)d_in[0];
    const float* x_kv = (const float*)d_in[1];
    const float* Wq   = (const float*)d_in[2];
    const float* bq   = (const float*)d_in[3];
    const float* Wqa  = (const float*)d_in[4];
    const float* bqa  = (const float*)d_in[5];
    const float* Wk   = (const float*)d_in[6];
    const float* bk   = (const float*)d_in[7];
    const float* Wka  = (const float*)d_in[8];
    const float* bka  = (const float*)d_in[9];
    const float* Wv   = (const float*)d_in[10];
    const float* bv   = (const float*)d_in[11];
    const float* Wt   = (const float*)d_in[12];
    const float* bt   = (const float*)d_in[13];
    const float* Wp   = (const float*)d_in[14];
    const float* bp   = (const float*)d_in[15];
    float* out = (float*)d_out;

    float *Q, *K, *S, *pq, *pk;
    __nv_bfloat16 *A1h, *A1l, *A2h, *A2l, *Wh, *Wl;
    cudaGetSymbolAddress((void**)&Q,   g_Q4);
    cudaGetSymbolAddress((void**)&K,   g_K4);
    cudaGetSymbolAddress((void**)&S,   g_S);
    cudaGetSymbolAddress((void**)&pq,  g_pq4);
    cudaGetSymbolAddress((void**)&pk,  g_pk4);
    cudaGetSymbolAddress((void**)&A1h, g_A1h);
    cudaGetSymbolAddress((void**)&A1l, g_A1l);
    cudaGetSymbolAddress((void**)&A2h, g_A2h);
    cudaGetSymbolAddress((void**)&A2l, g_A2l);
    cudaGetSymbolAddress((void**)&Wh,  g_Wh);
    cudaGetSymbolAddress((void**)&Wl,  g_Wl);

    cudaFuncSetAttribute(gemm_mma<0>, cudaFuncAttributeMaxDynamicSharedMemorySize, DSMEM);
    cudaFuncSetAttribute(gemm_mma<1>, cudaFuncAttributeMaxDynamicSharedMemorySize, DSMEM);
    cudaFuncSetAttribute(gemm_mma<2>, cudaFuncAttributeMaxDynamicSharedMemorySize, DSMEM);

    const dim3 gg(C_DIM / BN, MTOT / BM);                    // (8, 256)
    const int convAg = (int)((size_t)MTOT * C_DIM / 2048);   // 16384

    // 1: Q = x_q @ Wq + bq
    convW_kernel<<<1024, 256>>>(Wq, Wh, Wl);
    convA_kernel<<<convAg, 256>>>(x_q, A1h, A1l);
    gemm_mma<0><<<gg, 256, DSMEM>>>(A1h, A1l, Wh, Wl, bq, Q, nullptr, nullptr, nullptr);

    // query pooling
    logits_kernel<false><<<MTOT / 32, 256>>>(Q, Wqa, bqa, nullptr, S);
    softpool_kernel<<<NB * 16, 1024>>>(S, Q, pq);

    // 2: K = x_kv @ Wk + bk
    convW_kernel<<<1024, 256>>>(Wk, Wh, Wl);
    convA_kernel<<<convAg, 256>>>(x_kv, A2h, A2l);
    gemm_mma<0><<<gg, 256, DSMEM>>>(A2h, A2l, Wh, Wl, bk, K, nullptr, nullptr, nullptr);

    // gated key pooling
    logits_kernel<true><<<MTOT / 32, 256>>>(K, Wka, bka, pq, S);
    softpool_kernel<<<NB * 16, 1024>>>(S, K, pk);

    // 3: gated V = ((x_kv @ Wv + bv) * pk)  -> bf16 split directly (EPI 2)
    convW_kernel<<<1024, 256>>>(Wv, Wh, Wl);
    gemm_mma<2><<<gg, 256, DSMEM>>>(A2h, A2l, Wh, Wl, bv, nullptr, A1h, A1l, pk);

    // 4: T+Q = (gatedV) @ Wt + bt + Q  -> bf16 split (EPI 1), into A2 buffers
    convW_kernel<<<1024, 256>>>(Wt, Wh, Wl);
    gemm_mma<1><<<gg, 256, DSMEM>>>(A1h, A1l, Wh, Wl, bt, nullptr, A2h, A2l, Q);

    // 5: out = (T+Q) @ Wp + bp
    convW_kernel<<<1024, 256>>>(Wp, Wh, Wl);
    gemm_mma<0><<<gg, 256, DSMEM>>>(A2h, A2l, Wh, Wl, bp, out, nullptr, nullptr, nullptr);
}

// round 17
// speedup vs baseline: 2.7078x; 1.0567x over previous
#include <cuda_runtime.h>
#include <cuda_bf16.h>
#include <cstdint>

#define C_DIM 1024
#define NB 8
#define LSEQ 4096
#define MTOT (NB * LSEQ)   // 32768
#define BM 128
#define BN 256
#define KC 64
#define NCHUNK (C_DIM / KC)          // 16
#define STAGE_BYTES (96 * 1024)      // Ah 16K | Al 16K | Bh 32K | Bl 32K
#define DSMEM (1024 + 2 * STAGE_BYTES)

// ---------------- scratch --------------------------------------------------
__device__ float4 g_Q4 [(size_t)MTOT * C_DIM / 4];
__device__ float4 g_K4 [(size_t)MTOT * C_DIM / 4];
__device__ float  g_S  [(size_t)MTOT * 16];
__device__ float4 g_pq4[NB * C_DIM / 4];
__device__ float4 g_pk4[NB * C_DIM / 4];
__device__ uint4  g_A1h[(size_t)MTOT * C_DIM / 8];
__device__ uint4  g_A1l[(size_t)MTOT * C_DIM / 8];
__device__ uint4  g_A2h[(size_t)MTOT * C_DIM / 8];
__device__ uint4  g_A2l[(size_t)MTOT * C_DIM / 8];
__device__ uint4  g_Wh [5 * (size_t)C_DIM * C_DIM / 8];   // 5 weight slots
__device__ uint4  g_Wl [5 * (size_t)C_DIM * C_DIM / 8];

// ---------------- PTX helpers (sm_80-level only) ----------------------------
__device__ __forceinline__ uint32_t smem_u32(const void* p) {
    uint32_t a;
    asm("{ .reg .u64 t; cvta.to.shared.u64 t, %1; cvt.u32.u64 %0, t; }" : "=r"(a) : "l"(p));
    return a;
}
__device__ __forceinline__ void cp16(uint32_t dst, const void* src) {
    asm volatile("cp.async.cg.shared.global [%0], [%1], 16;" :: "r"(dst), "l"(src));
}
#define CP_COMMIT() asm volatile("cp.async.commit_group;" ::: "memory")
#define CP_WAIT(n)  asm volatile("cp.async.wait_group %0;" :: "n"(n) : "memory")

#define LDSM4(r, a) \
    asm volatile("ldmatrix.sync.aligned.m8n8.x4.shared.b16 {%0,%1,%2,%3}, [%4];" \
        : "=r"((r)[0]), "=r"((r)[1]), "=r"((r)[2]), "=r"((r)[3]) : "r"(a))

#define MMA16(d, a, b0, b1) \
    asm volatile("mma.sync.aligned.m16n8k16.row.col.f32.bf16.bf16.f32 " \
        "{%0,%1,%2,%3}, {%4,%5,%6,%7}, {%8,%9}, {%0,%1,%2,%3};" \
        : "+f"((d)[0]), "+f"((d)[1]), "+f"((d)[2]), "+f"((d)[3]) \
        : "r"((a)[0]), "r"((a)[1]), "r"((a)[2]), "r"((a)[3]), "r"(b0), "r"(b1))

// ---------------------------------------------------------------------------
// One K-chunk: A tile [128 x 64 bf16] hi/lo + B tile [256 x 64 bf16] hi/lo,
// each row = 128B, SW128 swizzle.
// ---------------------------------------------------------------------------
__device__ __forceinline__ void load_chunk(
    uint32_t sb,
    const __nv_bfloat16* __restrict__ Ah, const __nv_bfloat16* __restrict__ Al,
    const __nv_bfloat16* __restrict__ Bh, const __nv_bfloat16* __restrict__ Bl,
    int m0, int n0, int k0, int tid)
{
    const size_t kbyte = (size_t)k0 * 2;
    #pragma unroll
    for (int j = 0; j < 4; j++) {
        const int c = tid + j * 256;                  // 0..1023
        const int r = c >> 3, col = (c & 7) << 4;
        const uint32_t off = r * 128 + col;
        const uint32_t sw = off ^ ((off >> 3) & 0x70);
        const size_t goA = ((size_t)(m0 + r) << 11) + kbyte + col;
        cp16(sb + sw,          (const char*)Ah + goA);
        cp16(sb + 16384u + sw, (const char*)Al + goA);
    }
    #pragma unroll
    for (int j = 0; j < 8; j++) {
        const int c = tid + j * 256;                  // 0..2047
        const int r = c >> 3, col = (c & 7) << 4;
        const uint32_t off = r * 128 + col;
        const uint32_t sw = off ^ ((off >> 3) & 0x70);
        const size_t goB = ((size_t)(n0 + r) << 11) + kbyte + col;
        cp16(sb + 32768u + sw, (const char*)Bh + goB);
        cp16(sb + 65536u + sw, (const char*)Bl + goB);
    }
}

// ---------------------------------------------------------------------------
// bf16x3 GEMM via mma.sync: C = (Ah+Al) @ (Bh+Bl)^T + bias, B stored [n][k].
// Tile 128x256, warp tile 64x64 (2x4 warps).
// EPI 0: fp32 C.
// EPI 1: bf16 hi/lo split of (acc + bias + resid[row,col]).
// EPI 2: bf16 hi/lo split of (acc + bias) * gate[batch,col]  (resid = gate).
// ---------------------------------------------------------------------------
template <int EPI>
__global__ __launch_bounds__(256, 1)
void gemm_mma(const __nv_bfloat16* __restrict__ Ah, const __nv_bfloat16* __restrict__ Al,
              const __nv_bfloat16* __restrict__ Bh, const __nv_bfloat16* __restrict__ Bl,
              const float* __restrict__ bias, float* __restrict__ Cf,
              __nv_bfloat16* __restrict__ Oh, __nv_bfloat16* __restrict__ Ol,
              const float* __restrict__ resid)
{
    extern __shared__ char dsm[];
    const uint32_t tiles = (smem_u32(dsm) + 1023u) & ~1023u;
    const int tid  = threadIdx.x;
    const int lane = tid & 31;
    const int w    = tid >> 5;
    const int m0   = blockIdx.y * BM;
    const int n0   = blockIdx.x * BN;
    const int warp_m = (w >> 2) * 64;    // 0 or 64
    const int warp_n = (w & 3) * 64;     // 0,64,128,192

    const int row16 = (lane & 7) | (((lane >> 3) & 1) << 3);
    const int kcl   = lane >> 4;
    const int rA = warp_m + row16;
    const int rB = warp_n + row16;
    const uint32_t swA = (uint32_t)(rA & 7);
    const uint32_t swB = (uint32_t)(rB & 7);

    float acc[4][8][4];
    #pragma unroll
    for (int i = 0; i < 4; i++)
        #pragma unroll
        for (int j = 0; j < 8; j++)
            #pragma unroll
            for (int q = 0; q < 4; q++) acc[i][j][q] = 0.f;

    load_chunk(tiles, Ah, Al, Bh, Bl, m0, n0, 0, tid);
    CP_COMMIT();

    for (int i = 0; i < NCHUNK; i++) {
        const int s = i & 1;
        const uint32_t sb = tiles + (uint32_t)s * STAGE_BYTES;
        if (i + 1 < NCHUNK) {
            load_chunk(tiles + (uint32_t)(s ^ 1) * STAGE_BYTES,
                       Ah, Al, Bh, Bl, m0, n0, (i + 1) * KC, tid);
            CP_COMMIT();
            CP_WAIT(1);
        } else {
            CP_WAIT(0);
        }
        __syncthreads();

        const uint32_t aBaseH = sb           + (uint32_t)rA * 128;
        const uint32_t aBaseL = sb + 16384u  + (uint32_t)rA * 128;
        const uint32_t bBaseH = sb + 32768u  + (uint32_t)rB * 128;
        const uint32_t bBaseL = sb + 65536u  + (uint32_t)rB * 128;

        #pragma unroll
        for (int ks = 0; ks < 4; ks++) {
            const uint32_t aoff = (uint32_t)(((ks * 2 + kcl) ^ swA) << 4);
            const uint32_t boff = (uint32_t)(((ks * 2 + kcl) ^ swB) << 4);

            uint32_t ahf[4][4], alf[4][4], bhf[4][4];
            #pragma unroll
            for (int mf = 0; mf < 4; mf++) LDSM4(ahf[mf], aBaseH + mf * 2048u + aoff);
            #pragma unroll
            for (int nb = 0; nb < 4; nb++) LDSM4(bhf[nb], bBaseH + nb * 2048u + boff);
            #pragma unroll
            for (int mf = 0; mf < 4; mf++) LDSM4(alf[mf], aBaseL + mf * 2048u + aoff);

            // sweep 1: Ah * Bh
            #pragma unroll
            for (int mf = 0; mf < 4; mf++)
                #pragma unroll
                for (int nf = 0; nf < 8; nf++) {
                    const int nb = nf >> 1, sel = nf & 1;
                    MMA16(acc[mf][nf], ahf[mf], bhf[nb][sel], bhf[nb][sel + 2]);
                }
            // sweep 2: Al * Bh
            #pragma unroll
            for (int mf = 0; mf < 4; mf++)
                #pragma unroll
                for (int nf = 0; nf < 8; nf++) {
                    const int nb = nf >> 1, sel = nf & 1;
                    MMA16(acc[mf][nf], alf[mf], bhf[nb][sel], bhf[nb][sel + 2]);
                }
            // sweep 3: Ah * Bl  (Bl loaded into alf's registers' slots)
            uint32_t blf[4][4];
            #pragma unroll
            for (int nb = 0; nb < 4; nb++) LDSM4(blf[nb], bBaseL + nb * 2048u + boff);
            #pragma unroll
            for (int mf = 0; mf < 4; mf++)
                #pragma unroll
                for (int nf = 0; nf < 8; nf++) {
                    const int nb = nf >> 1, sel = nf & 1;
                    MMA16(acc[mf][nf], ahf[mf], blf[nb][sel], blf[nb][sel + 2]);
                }
        }
        __syncthreads();
    }

    // ---------------- epilogue ----------------
    const int tr = lane >> 2;
    const int tc = (lane & 3) * 2;
    const int bat = m0 / LSEQ;
    const float* gp = (EPI == 2) ? (resid + (size_t)bat * C_DIM) : nullptr;

    #pragma unroll
    for (int nf = 0; nf < 8; nf++) {
        const int col = n0 + warp_n + nf * 8 + tc;
        const float b0 = bias[col], b1 = bias[col + 1];
        float g0 = 1.f, g1 = 1.f;
        if (EPI == 2) { g0 = gp[col]; g1 = gp[col + 1]; }
        #pragma unroll
        for (int mf = 0; mf < 4; mf++) {
            #pragma unroll
            for (int half = 0; half < 2; half++) {
                const int row = m0 + warp_m + mf * 16 + tr + half * 8;
                float v0 = acc[mf][nf][half * 2 + 0] + b0;
                float v1 = acc[mf][nf][half * 2 + 1] + b1;
                if (EPI == 0) {
                    *(float2*)(Cf + (size_t)row * C_DIM + col) = make_float2(v0, v1);
                } else {
                    if (EPI == 1) {
                        const float2 r2 = *(const float2*)(resid + (size_t)row * C_DIM + col);
                        v0 += r2.x; v1 += r2.y;
                    } else {
                        v0 *= g0; v1 *= g1;
                    }
                    const __nv_bfloat16 h0 = __float2bfloat16(v0);
                    const __nv_bfloat16 h1 = __float2bfloat16(v1);
                    const __nv_bfloat16 l0 = __float2bfloat16(v0 - __bfloat162float(h0));
                    const __nv_bfloat16 l1 = __float2bfloat16(v1 - __bfloat162float(h1));
                    __nv_bfloat162 hp; hp.x = h0; hp.y = h1;
                    __nv_bfloat162 lp; lp.x = l0; lp.y = l1;
                    *(__nv_bfloat162*)(Oh + (size_t)row * C_DIM + col) = hp;
                    *(__nv_bfloat162*)(Ol + (size_t)row * C_DIM + col) = lp;
                }
            }
        }
    }
}

// ---------------- activation split ------------------------------------------
__global__ __launch_bounds__(256)
void convA_kernel(const float* __restrict__ X,
                  __nv_bfloat16* __restrict__ Ah, __nv_bfloat16* __restrict__ Al)
{
    const size_t e = ((size_t)blockIdx.x * 256 + threadIdx.x) * 8;
    float v[8];
    *(float4*)(v)     = *(const float4*)(X + e);
    *(float4*)(v + 4) = *(const float4*)(X + e + 4);
    __nv_bfloat16 hb[8], lb[8];
    #pragma unroll
    for (int j = 0; j < 8; j++) {
        __nv_bfloat16 h = __float2bfloat16(v[j]);
        hb[j] = h;
        lb[j] = __float2bfloat16(v[j] - __bfloat162float(h));
    }
    *(uint4*)(Ah + e) = *(uint4*)hb;
    *(uint4*)(Al + e) = *(uint4*)lb;
}

// ---------------- all-5 weight transpose+split: W[k][n] -> slot g of [n][k] -
__global__ __launch_bounds__(256)
void convW5_kernel(const float* __restrict__ W0, const float* __restrict__ W1,
                   const float* __restrict__ W2, const float* __restrict__ W3,
                   const float* __restrict__ W4,
                   __nv_bfloat16* __restrict__ WhB, __nv_bfloat16* __restrict__ WlB)
{
    __shared__ float t[32][33];
    const int g = blockIdx.y;
    const float* W = (g == 0) ? W0 : (g == 1) ? W1 : (g == 2) ? W2 : (g == 3) ? W3 : W4;
    __nv_bfloat16* Wh = WhB + (size_t)g * C_DIM * C_DIM;
    __nv_bfloat16* Wl = WlB + (size_t)g * C_DIM * C_DIM;

    const int bx = blockIdx.x & 31, by = blockIdx.x >> 5;
    const int x = threadIdx.x & 31, y = threadIdx.x >> 5;
    #pragma unroll
    for (int j = 0; j < 4; j++)
        t[y + j * 8][x] = W[(size_t)(by * 32 + y + j * 8) * C_DIM + bx * 32 + x];
    __syncthreads();
    #pragma unroll
    for (int j = 0; j < 4; j++) {
        const float v = t[x][y + j * 8];
        const __nv_bfloat16 h = __float2bfloat16(v);
        const size_t o = (size_t)(bx * 32 + y + j * 8) * C_DIM + by * 32 + x;
        Wh[o] = h;
        Wl[o] = __float2bfloat16(v - __bfloat162float(h));
    }
}

// ---------------- logits: 4 rows per warp (R10 form) ------------------------
template <bool GATE>
__global__ __launch_bounds__(256)
void logits_kernel(const float* __restrict__ X, const float* __restrict__ W,
                   const float* __restrict__ b, const float* __restrict__ gate,
                   float* __restrict__ S)
{
    const int warp = threadIdx.x >> 5, lane = threadIdx.x & 31;
    const int r0 = blockIdx.x * 32 + warp * 4;
    const int bat = r0 >> 12;
    const float* gp = GATE ? (gate + (size_t)bat * C_DIM) : nullptr;

    float acc[4][16];
    #pragma unroll
    for (int r = 0; r < 4; r++)
        #pragma unroll
        for (int h = 0; h < 16; h++) acc[r][h] = 0.f;

    for (int c = lane; c < C_DIM; c += 32) {
        float a[4];
        #pragma unroll
        for (int r = 0; r < 4; r++) a[r] = X[(size_t)(r0 + r) * C_DIM + c];
        if (GATE) {
            const float g = gp[c];
            #pragma unroll
            for (int r = 0; r < 4; r++) a[r] *= g;
        }
        const float4* wp = (const float4*)(W + (size_t)c * 16);
        const float4 w0 = wp[0], w1 = wp[1], w2 = wp[2], w3 = wp[3];
        const float wv[16] = { w0.x, w0.y, w0.z, w0.w, w1.x, w1.y, w1.z, w1.w,
                               w2.x, w2.y, w2.z, w2.w, w3.x, w3.y, w3.z, w3.w };
        #pragma unroll
        for (int r = 0; r < 4; r++)
            #pragma unroll
            for (int h = 0; h < 16; h++) acc[r][h] += a[r] * wv[h];
    }
    #pragma unroll
    for (int r = 0; r < 4; r++)
        #pragma unroll
        for (int h = 0; h < 16; h++)
            #pragma unroll
            for (int off = 16; off; off >>= 1)
                acc[r][h] += __shfl_xor_sync(0xffffffffu, acc[r][h], off);
    if (lane == 0) {
        const float scale = 0.125f;
        #pragma unroll
        for (int r = 0; r < 4; r++)
            #pragma unroll
            for (int h = 0; h < 16; h++)
                S[(size_t)(r0 + r) * 16 + h] = (acc[r][h] + b[h]) * scale;
    }
}

// ---------------- softmax over L + pooling ----------------------------------
__global__ __launch_bounds__(1024)
void softpool_kernel(const float* __restrict__ S, const float* __restrict__ X,
                     float* __restrict__ pooled)
{
    __shared__ float red[1024];
    const int nh = blockIdx.x, n = nh >> 4, h = nh & 15;
    const int tid = threadIdx.x;
    const float* sp = S + (size_t)n * LSEQ * 16 + h;

    float m = -1e30f;
    for (int l = tid; l < LSEQ; l += 1024) m = fmaxf(m, sp[(size_t)l * 16]);
    red[tid] = m; __syncthreads();
    for (int s = 512; s; s >>= 1) { if (tid < s) red[tid] = fmaxf(red[tid], red[tid + s]); __syncthreads(); }
    m = red[0]; __syncthreads();

    float sum = 0.f;
    for (int l = tid; l < LSEQ; l += 1024) sum += __expf(sp[(size_t)l * 16] - m);
    red[tid] = sum; __syncthreads();
    for (int s = 512; s; s >>= 1) { if (tid < s) red[tid] += red[tid + s]; __syncthreads(); }
    const float invZ = 1.f / red[0]; __syncthreads();

    const int d = tid & 63, lg = tid >> 6;
    const float* xp = X + (size_t)n * LSEQ * C_DIM + h * 64 + d;
    float acc = 0.f;
    for (int l = lg; l < LSEQ; l += 16) {
        float wgt = __expf(sp[(size_t)l * 16] - m) * invZ;
        acc += wgt * xp[(size_t)l * C_DIM];
    }
    red[tid] = acc; __syncthreads();
    if (tid < 64) {
        float s = 0.f;
        #pragma unroll
        for (int g = 0; g < 16; g++) s += red[g * 64 + d];
        pooled[(size_t)n * C_DIM + h * 64 + d] = s;
    }
}

// ---------------------------------------------------------------------------
extern "C" void kernel_launch(void* const* d_in, const int* in_sizes, int n_in,
                              void* d_out, int out_size)
{
    const float* x_q  = (const float*)d_in[0];
    const float* x_kv = (const float*)d_in[1];
    const float* Wq   = (const float*)d_in[2];
    const float* bq   = (const float*)d_in[3];
    const float* Wqa  = (const float*)d_in[4];
    const float* bqa  = (const float*)d_in[5];
    const float* Wk   = (const float*)d_in[6];
    const float* bk   = (const float*)d_in[7];
    const float* Wka  = (const float*)d_in[8];
    const float* bka  = (const float*)d_in[9];
    const float* Wv   = (const float*)d_in[10];
    const float* bv   = (const float*)d_in[11];
    const float* Wt   = (const float*)d_in[12];
    const float* bt   = (const float*)d_in[13];
    const float* Wp   = (const float*)d_in[14];
    const float* bp   = (const float*)d_in[15];
    float* out = (float*)d_out;

    float *Q, *K, *S, *pq, *pk;
    __nv_bfloat16 *A1h, *A1l, *A2h, *A2l, *Wh, *Wl;
    cudaGetSymbolAddress((void**)&Q,   g_Q4);
    cudaGetSymbolAddress((void**)&K,   g_K4);
    cudaGetSymbolAddress((void**)&S,   g_S);
    cudaGetSymbolAddress((void**)&pq,  g_pq4);
    cudaGetSymbolAddress((void**)&pk,  g_pk4);
    cudaGetSymbolAddress((void**)&A1h, g_A1h);
    cudaGetSymbolAddress((void**)&A1l, g_A1l);
    cudaGetSymbolAddress((void**)&A2h, g_A2h);
    cudaGetSymbolAddress((void**)&A2l, g_A2l);
    cudaGetSymbolAddress((void**)&Wh,  g_Wh);
    cudaGetSymbolAddress((void**)&Wl,  g_Wl);

    cudaFuncSetAttribute(gemm_mma<0>, cudaFuncAttributeMaxDynamicSharedMemorySize, DSMEM);
    cudaFuncSetAttribute(gemm_mma<1>, cudaFuncAttributeMaxDynamicSharedMemorySize, DSMEM);
    cudaFuncSetAttribute(gemm_mma<2>, cudaFuncAttributeMaxDynamicSharedMemorySize, DSMEM);

    const size_t WSZ = (size_t)C_DIM * C_DIM;
    const dim3 gg(C_DIM / BN, MTOT / BM);                    // (4, 256)
    const int convAg = (int)((size_t)MTOT * C_DIM / 2048);   // 16384

    // all weight conversions + both activation splits up front
    convW5_kernel<<<dim3(1024, 5), 256>>>(Wq, Wk, Wv, Wt, Wp, Wh, Wl);
    convA_kernel<<<convAg, 256>>>(x_q,  A1h, A1l);
    convA_kernel<<<convAg, 256>>>(x_kv, A2h, A2l);

    // 1: Q = x_q @ Wq + bq
    gemm_mma<0><<<gg, 256, DSMEM>>>(A1h, A1l, Wh, Wl, bq, Q, nullptr, nullptr, nullptr);

    // query pooling
    logits_kernel<false><<<MTOT / 32, 256>>>(Q, Wqa, bqa, nullptr, S);
    softpool_kernel<<<NB * 16, 1024>>>(S, Q, pq);

    // 2: K = x_kv @ Wk + bk
    gemm_mma<0><<<gg, 256, DSMEM>>>(A2h, A2l, Wh + WSZ, Wl + WSZ, bk, K, nullptr, nullptr, nullptr);

    // gated key pooling
    logits_kernel<true><<<MTOT / 32, 256>>>(K, Wka, bka, pq, S);
    softpool_kernel<<<NB * 16, 1024>>>(S, K, pk);

    // 3: gated V = ((x_kv @ Wv + bv) * pk) -> bf16 split (EPI 2) into A1
    gemm_mma<2><<<gg, 256, DSMEM>>>(A2h, A2l, Wh + 2 * WSZ, Wl + 2 * WSZ, bv, nullptr, A1h, A1l, pk);

    // 4: T+Q = gatedV @ Wt + bt + Q -> bf16 split (EPI 1) into A2
    gemm_mma<1><<<gg, 256, DSMEM>>>(A1h, A1l, Wh + 3 * WSZ, Wl + 3 * WSZ, bt, nullptr, A2h, A2l, Q);

    // 5: out = (T+Q) @ Wp + bp
    gemm_mma<0><<<gg, 256, DSMEM>>>(A2h, A2l, Wh + 4 * WSZ, Wl + 4 * WSZ, bp, out, nullptr, nullptr, nullptr);
}